// round 10
// baseline (speedup 1.0000x reference)
#include <cuda_runtime.h>

// Gray-Scott reaction-diffusion residual, v10 = v4 + packed f32x2 math.
// y-march (chunked) + float2(z-pair) per thread; ALL per-pair arithmetic done
// with sm_103a add/mul/fma.rn.f32x2 on 64-bit packed registers.
// Input:  output [50, 2, 100, 100, 100] fp32  (d_in[0])
// Output: f_u (48,96,96,96) then f_v (48,96,96,96), fp32.

typedef unsigned long long ull;

#define SLICE_C  1000000
#define STRIDE_T 2000000
#define PLANE    10000
#define ROW      100
#define OUTE     96
#define OUTP     (96*96)
#define OUTVOL   (96*96*96)
#define YCHUNK   24

__device__ __forceinline__ ull ADD2(ull a, ull b) {
    ull r; asm("add.rn.f32x2 %0,%1,%2;" : "=l"(r) : "l"(a), "l"(b)); return r;
}
__device__ __forceinline__ ull MUL2(ull a, ull b) {
    ull r; asm("mul.rn.f32x2 %0,%1,%2;" : "=l"(r) : "l"(a), "l"(b)); return r;
}
__device__ __forceinline__ ull FMA2(ull a, ull b, ull c) {
    ull r; asm("fma.rn.f32x2 %0,%1,%2,%3;" : "=l"(r) : "l"(a), "l"(b), "l"(c)); return r;
}
__device__ __forceinline__ ull PK(float x, float y) {
    ull r; asm("mov.b64 %0,{%1,%2};" : "=l"(r) : "f"(x), "f"(y)); return r;
}
__device__ __forceinline__ void UNPK(ull a, float& x, float& y) {
    asm("mov.b64 {%0,%1},%2;" : "=f"(x), "=f"(y) : "l"(a));
}

#define LDU(p, off) (*(const ull*)((p) + (off)))

__global__ void __launch_bounds__(192) gs_residual_v10(
    const float* __restrict__ in, float* __restrict__ out)
{
    const int zp = threadIdx.x;                    // 0..47 (z pair)
    const int z  = zp * 2;
    const int x  = blockIdx.x * 4 + threadIdx.y;   // 0..95
    const int yb = blockIdx.y * YCHUNK;
    const int t  = blockIdx.z;

    const float* __restrict__ u = in + (long long)t * STRIDE_T;
    const float* __restrict__ v = u + SLICE_C;
    const float* __restrict__ un_p = u + STRIDE_T;
    const float* __restrict__ vn_p = v + STRIDE_T;

    const int base = (x + 2) * ROW + (z + 2);

    // packed coefficients (INV_DX2 folded into DU/DV; 1/DT folded into linear terms)
    const float S0f = -1.0f / 12.0f;
    const float S1f =  4.0f / 3.0f;
    const float SCf = -7.5f;
    const float INV_DX2 = (48.0f / 100.0f) * (48.0f / 100.0f);   // 1/DX^2
    const float DUf = 0.2f * INV_DX2;
    const float DVf = 0.1f * INV_DX2;
    const float FFf = 0.025f, KKf = 0.055f;

    const ull cS0  = PK(S0f, S0f);
    const ull cS1  = PK(S1f, S1f);
    const ull cSC  = PK(SCf, SCf);
    const ull cDU  = PK(DUf, DUf);
    const ull cDV  = PK(DVf, DVf);
    const ull cFF  = PK(FFf, FFf);
    const ull cUL  = PK(2.0f - FFf, 2.0f - FFf);          // coeff of u in f_u
    const ull cVL  = PK(2.0f - FFf - KKf, 2.0f - FFf - KKf); // coeff of v in f_v
    const ull cM2  = PK(-2.0f, -2.0f);
    const ull cM1  = PK(-1.0f, -1.0f);

    // register queue of packed centers for input planes yb .. yb+3
    ull qu[5], qv[5];
#pragma unroll
    for (int i = 0; i < 4; i++) {
        qu[i] = LDU(u, (yb + i) * PLANE + base);
        qv[i] = LDU(v, (yb + i) * PLANE + base);
    }

    int oidx = t * OUTVOL + yb * OUTP + x * OUTE + z;

#pragma unroll 2
    for (int yy = 0; yy < YCHUNK; yy++) {
        const int yc = yb + yy;
        const int pc = (yc + 2) * PLANE + base;

        // new far-plane centers (y+4)
        qu[4] = LDU(u, (yc + 4) * PLANE + base);
        qv[4] = LDU(v, (yc + 4) * PLANE + base);

        // z-halo: left = inputs z, z+1 ; right = inputs z+4, z+5
        ull uzl = LDU(u, pc - 2);
        ull uzr = LDU(u, pc + 2);
        ull vzl = LDU(v, pc - 2);
        ull vzr = LDU(v, pc + 2);

        // x taps
        ull uxm1 = LDU(u, pc - ROW);
        ull uxp1 = LDU(u, pc + ROW);
        ull uxm2 = LDU(u, pc - 2 * ROW);
        ull uxp2 = LDU(u, pc + 2 * ROW);
        ull vxm1 = LDU(v, pc - ROW);
        ull vxp1 = LDU(v, pc + ROW);
        ull vxm2 = LDU(v, pc - 2 * ROW);
        ull vxp2 = LDU(v, pc + 2 * ROW);

        // t+1 centers
        ull unx = LDU(un_p, pc);
        ull vnx = LDU(vn_p, pc);

        ull uc = qu[2];
        ull vc = qv[2];

        // ---- u laplacian (packed) ----
        // s1 z-component: point0 taps (uzl.y, uc.y), point1 taps (uc.x, uzr.x)
        float uzl_x, uzl_y, uzr_x, uzr_y, uc_x, uc_y;
        UNPK(uzl, uzl_x, uzl_y);
        UNPK(uzr, uzr_x, uzr_y);
        UNPK(uc,  uc_x,  uc_y);
        ull ua1 = PK(uzl_y, uc_x);
        ull ua2 = PK(uc_y, uzr_x);
        ull us1 = ADD2(ADD2(ua1, ua2),
                       ADD2(ADD2(uxm1, uxp1), ADD2(qu[1], qu[3])));
        ull us2 = ADD2(ADD2(uzl, uzr),
                       ADD2(ADD2(uxm2, uxp2), ADD2(qu[0], qu[4])));
        ull lpu = FMA2(us1, cS1, FMA2(us2, cS0, MUL2(uc, cSC)));  // lap * DX^2

        // ---- v laplacian (packed) ----
        float vzl_x, vzl_y, vzr_x, vzr_y, vc_x, vc_y;
        UNPK(vzl, vzl_x, vzl_y);
        UNPK(vzr, vzr_x, vzr_y);
        UNPK(vc,  vc_x,  vc_y);
        ull va1 = PK(vzl_y, vc_x);
        ull va2 = PK(vc_y, vzr_x);
        ull vs1 = ADD2(ADD2(va1, va2),
                       ADD2(ADD2(vxm1, vxp1), ADD2(qv[1], qv[3])));
        ull vs2 = ADD2(ADD2(vzl, vzr),
                       ADD2(ADD2(vxm2, vxp2), ADD2(qv[0], qv[4])));
        ull lpv = FMA2(vs1, cS1, FMA2(vs2, cS0, MUL2(vc, cSC)));

        // ---- reaction + time derivative (packed) ----
        // w = u*v*v
        ull w = MUL2(MUL2(vc, vc), uc);
        // f_u = DU'*lpu - w + FF + u*(2-FF) - 2*un
        ull t1 = FMA2(uc, cUL, cFF);
        t1 = FMA2(unx, cM2, t1);
        t1 = FMA2(w, cM1, t1);
        ull fu = FMA2(lpu, cDU, t1);
        // f_v = DV'*lpv + w + v*(2-FF-KK) - 2*vn
        ull t2 = MUL2(vc, cVL);
        t2 = FMA2(vnx, cM2, t2);
        t2 = ADD2(w, t2);
        ull fv = FMA2(lpv, cDV, t2);

        *(ull*)(out + oidx) = fu;
        *(ull*)(out + 48 * OUTVOL + oidx) = fv;
        oidx += OUTP;

        // shift queues
        qu[0] = qu[1]; qu[1] = qu[2]; qu[2] = qu[3]; qu[3] = qu[4];
        qv[0] = qv[1]; qv[1] = qv[2]; qv[2] = qv[3]; qv[3] = qv[4];
    }
}

extern "C" void kernel_launch(void* const* d_in, const int* in_sizes, int n_in,
                              void* d_out, int out_size)
{
    const float* in = (const float*)d_in[0];
    float* out = (float*)d_out;
    dim3 grid(24, 4, 48);    // x-tiles (96/4), y-chunks, t
    dim3 block(48, 4);       // z-pairs, x within tile
    gs_residual_v10<<<grid, block>>>(in, out);
}

// round 11
// speedup vs baseline: 1.2300x; 1.2300x over previous
#include <cuda_runtime.h>

// Gray-Scott reaction-diffusion residual, v11 = v7 (x-pair per thread) + unroll 2.
// y-march + float2 in z + x-PAIR per thread (4 spatial pts / 8 values per iter).
// Input:  output [50, 2, 100, 100, 100] fp32  (d_in[0])
// Output: f_u (48,96,96,96) then f_v (48,96,96,96), fp32.

#define SLICE_C  1000000      // u->v channel offset (floats)
#define STRIDE_T 2000000      // per-timestep offset (floats)
#define PLANE    10000
#define ROW      100
#define OUTE     96
#define OUTP     (96*96)
#define OUTVOL   (96*96*96)
#define YCHUNK   24

#define LD2(p, off) (*(const float2*)((p) + (off)))

__device__ __forceinline__ float2 lap2(
    float2 c, float2 zl, float2 zr,
    float2 x1a, float2 x1b, float2 x2a, float2 x2b,
    float2 y1a, float2 y1b, float2 y2a, float2 y2b)
{
    const float S0 = -1.0f / 12.0f;
    const float S1 = 4.0f / 3.0f;
    const float SC = -7.5f;
    const float DXv = 100.0f / 48.0f;
    const float INV_DX2 = 1.0f / (DXv * DXv);
    float s1x = zl.y + c.y + x1a.x + x1b.x + y1a.x + y1b.x;
    float s2x = zl.x + zr.x + x2a.x + x2b.x + y2a.x + y2b.x;
    float s1y = c.x + zr.x + x1a.y + x1b.y + y1a.y + y1b.y;
    float s2y = zl.y + zr.y + x2a.y + x2b.y + y2a.y + y2b.y;
    float2 r;
    r.x = (S1 * s1x + S0 * s2x + SC * c.x) * INV_DX2;
    r.y = (S1 * s1y + S0 * s2y + SC * c.y) * INV_DX2;
    return r;
}

__global__ void __launch_bounds__(96, 5) gs_residual_v11(
    const float* __restrict__ in, float* __restrict__ out)
{
    const int zp = threadIdx.x;                    // 0..47 (z pair)
    const int z  = zp * 2;
    const int x  = blockIdx.x * 4 + threadIdx.y * 2;   // thread handles rows x, x+1
    const int yb = blockIdx.y * YCHUNK;
    const int t  = blockIdx.z;

    // p -> center f2 of input row (x+2), plane yb, channel u, time t.
    const float* p  = in + (long long)t * STRIDE_T
                         + (long long)yb * PLANE
                         + (x + 2) * ROW + (z + 2);
    const float* pn = p + STRIDE_T;                // t+1 (center-plane reads only)

    const float INV_DT = 2.0f;
    const float DU = 0.2f, DV = 0.1f, FF = 0.025f, KK = 0.055f;

    // y-queue of centers for the two rows: [plane][row 0/1]
    float2 qu[5][2], qv[5][2];
#pragma unroll
    for (int i = 0; i < 4; i++) {
        qu[i][0] = LD2(p, i * PLANE);
        qu[i][1] = LD2(p, i * PLANE + ROW);
        qv[i][0] = LD2(p, i * PLANE + SLICE_C);
        qv[i][1] = LD2(p, i * PLANE + ROW + SLICE_C);
    }

    float* ou = out + t * OUTVOL + yb * OUTP + x * OUTE + z;
    float* ov = ou + 48 * OUTVOL;

#pragma unroll 2
    for (int yy = 0; yy < YCHUNK; yy++) {
        // ---- channel u loads (12 f2) ----
        float2 qu40 = LD2(p, 4 * PLANE);
        float2 qu41 = LD2(p, 4 * PLANE + ROW);
        float2 uzl0 = LD2(p, 2 * PLANE - 2);
        float2 uzr0 = LD2(p, 2 * PLANE + 2);
        float2 uzl1 = LD2(p, 2 * PLANE + ROW - 2);
        float2 uzr1 = LD2(p, 2 * PLANE + ROW + 2);
        float2 uxa  = LD2(p, 2 * PLANE - 2 * ROW);   // row x
        float2 uxb  = LD2(p, 2 * PLANE - ROW);       // row x+1
        float2 uxc  = LD2(p, 2 * PLANE + 2 * ROW);   // row x+4
        float2 uxd  = LD2(p, 2 * PLANE + 3 * ROW);   // row x+5
        float2 un0  = LD2(pn, 2 * PLANE);
        float2 un1  = LD2(pn, 2 * PLANE + ROW);
        // ---- channel v loads (12 f2) ----
        float2 qv40 = LD2(p, 4 * PLANE + SLICE_C);
        float2 qv41 = LD2(p, 4 * PLANE + ROW + SLICE_C);
        float2 vzl0 = LD2(p, 2 * PLANE - 2 + SLICE_C);
        float2 vzr0 = LD2(p, 2 * PLANE + 2 + SLICE_C);
        float2 vzl1 = LD2(p, 2 * PLANE + ROW - 2 + SLICE_C);
        float2 vzr1 = LD2(p, 2 * PLANE + ROW + 2 + SLICE_C);
        float2 vxa  = LD2(p, 2 * PLANE - 2 * ROW + SLICE_C);
        float2 vxb  = LD2(p, 2 * PLANE - ROW + SLICE_C);
        float2 vxc  = LD2(p, 2 * PLANE + 2 * ROW + SLICE_C);
        float2 vxd  = LD2(p, 2 * PLANE + 3 * ROW + SLICE_C);
        float2 vn0  = LD2(pn, 2 * PLANE + SLICE_C);
        float2 vn1  = LD2(pn, 2 * PLANE + ROW + SLICE_C);

        qu[4][0] = qu40; qu[4][1] = qu41;
        qv[4][0] = qv40; qv[4][1] = qv41;

        // ---- laplacians ----
        // output row x:   x-taps ±1 -> rows x+1 (uxb), x+3 (qu[2][1]); ±2 -> rows x (uxa), x+4 (uxc)
        float2 lapu0 = lap2(qu[2][0], uzl0, uzr0, uxb, qu[2][1], uxa, uxc,
                            qu[1][0], qu[3][0], qu[0][0], qu[4][0]);
        float2 lapv0 = lap2(qv[2][0], vzl0, vzr0, vxb, qv[2][1], vxa, vxc,
                            qv[1][0], qv[3][0], qv[0][0], qv[4][0]);
        // output row x+1: x-taps ±1 -> rows x+2 (qu[2][0]), x+4 (uxc); ±2 -> rows x+1 (uxb), x+5 (uxd)
        float2 lapu1 = lap2(qu[2][1], uzl1, uzr1, qu[2][0], uxc, uxb, uxd,
                            qu[1][1], qu[3][1], qu[0][1], qu[4][1]);
        float2 lapv1 = lap2(qv[2][1], vzl1, vzr1, qv[2][0], vxc, vxb, vxd,
                            qv[1][1], qv[3][1], qv[0][1], qv[4][1]);

        // ---- reaction + time derivative, row x ----
        {
            float2 uc = qu[2][0], vc = qv[2][0];
            float uvv0 = uc.x * vc.x * vc.x;
            float uvv1 = uc.y * vc.y * vc.y;
            float2 fu, fv;
            fu.x = DU * lapu0.x - uvv0 + FF * (1.0f - uc.x) - (un0.x - uc.x) * INV_DT;
            fu.y = DU * lapu0.y - uvv1 + FF * (1.0f - uc.y) - (un0.y - uc.y) * INV_DT;
            fv.x = DV * lapv0.x + uvv0 - (FF + KK) * vc.x - (vn0.x - vc.x) * INV_DT;
            fv.y = DV * lapv0.y + uvv1 - (FF + KK) * vc.y - (vn0.y - vc.y) * INV_DT;
            *(float2*)ou = fu;
            *(float2*)ov = fv;
        }
        // ---- reaction + time derivative, row x+1 ----
        {
            float2 uc = qu[2][1], vc = qv[2][1];
            float uvv0 = uc.x * vc.x * vc.x;
            float uvv1 = uc.y * vc.y * vc.y;
            float2 fu, fv;
            fu.x = DU * lapu1.x - uvv0 + FF * (1.0f - uc.x) - (un1.x - uc.x) * INV_DT;
            fu.y = DU * lapu1.y - uvv1 + FF * (1.0f - uc.y) - (un1.y - uc.y) * INV_DT;
            fv.x = DV * lapv1.x + uvv0 - (FF + KK) * vc.x - (vn1.x - vc.x) * INV_DT;
            fv.y = DV * lapv1.y + uvv1 - (FF + KK) * vc.y - (vn1.y - vc.y) * INV_DT;
            *(float2*)(ou + OUTE) = fu;
            *(float2*)(ov + OUTE) = fv;
        }

        ou += OUTP;
        ov += OUTP;
        p  += PLANE;
        pn += PLANE;

        // shift queues
#pragma unroll
        for (int i = 0; i < 4; i++) {
            qu[i][0] = qu[i + 1][0]; qu[i][1] = qu[i + 1][1];
            qv[i][0] = qv[i + 1][0]; qv[i][1] = qv[i + 1][1];
        }
    }
}

extern "C" void kernel_launch(void* const* d_in, const int* in_sizes, int n_in,
                              void* d_out, int out_size)
{
    const float* in = (const float*)d_in[0];
    float* out = (float*)d_out;
    dim3 grid(24, 4, 48);    // x-tiles (4 x-rows each), y-chunks, t
    dim3 block(48, 2);       // z-pairs, x-pairs
    gs_residual_v11<<<grid, block>>>(in, out);
}